// round 3
// baseline (speedup 1.0000x reference)
#include <cuda_runtime.h>

// Problem constants
#define SRC_HW   64
#define CELLS    4096        // 64*64 flow cells per batch-slice
#define CH       256
#define NB       4           // output batches
#define NN       4           // accumulated slices (num)
#define HO       192         // output H = W = 3*64
#define NBB      16          // NB*NN batch-slices

// Precomputed per-(bb, cell) metadata:
//  .x = bitcast int: (y0 << 16) | (x0 & 0xFFFF)   (y0 = floor(cy+fy), x0 = floor(cx+fx))
//  .y = m * (1 - ay)
//  .z = m * ay
//  .w = ax
__device__ float4 g_meta[NBB * CELLS];   // 1 MB static scratch (allowed)

__global__ void meta_kernel(const float* __restrict__ flow,
                            const float* __restrict__ masks) {
    int idx = blockIdx.x * blockDim.x + threadIdx.x;
    if (idx >= NBB * CELLS) return;
    int bb   = idx >> 12;
    int cell = idx & (CELLS - 1);
    int cy = cell >> 6;
    int cx = cell & 63;

    float fy = flow[((size_t)(bb * 2 + 0)) * CELLS + cell];
    float fx = flow[((size_t)(bb * 2 + 1)) * CELLS + cell];
    float m  = masks[(size_t)bb * CELLS + cell];

    float by = (float)cy + fy;
    float bx = (float)cx + fx;
    float y0f = floorf(by);
    float x0f = floorf(bx);
    float ay = by - y0f;
    float ax = bx - x0f;
    int y0 = (int)y0f;
    int x0 = (int)x0f;

    int packed = ((y0 & 0xFFFF) << 16) | (x0 & 0xFFFF);
    g_meta[idx] = make_float4(__int_as_float(packed), m * (1.0f - ay), m * ay, ax);
}

// One block per (channel, batch). SMEM-staged source planes (2 at a time),
// each thread owns 8 cells, accumulates 9 outputs per cell over all 4 n.
__global__ __launch_bounds__(512, 1)
void extract_kernel(const float* __restrict__ src, float* __restrict__ out) {
    const int c = blockIdx.x;   // 0..255
    const int b = blockIdx.y;   // 0..3
    const int t = threadIdx.x;  // 0..511

    __shared__ float4 planes4[2][CELLS / 4];   // 2 x 16KB

    float acc[8][9];
#pragma unroll
    for (int j = 0; j < 8; j++)
#pragma unroll
        for (int q = 0; q < 9; q++) acc[j][q] = 0.0f;

#pragma unroll
    for (int ph = 0; ph < 2; ph++) {
        // Cooperative load of planes for n = 2*ph and 2*ph+1
#pragma unroll
        for (int u = 0; u < 2; u++) {
            int n  = 2 * ph + u;
            int bb = n * NB + b;
            const float4* sp = (const float4*)(src + ((size_t)(bb * CH + c)) * CELLS);
            planes4[u][t]       = sp[t];
            planes4[u][t + 512] = sp[t + 512];
        }
        __syncthreads();

#pragma unroll
        for (int u = 0; u < 2; u++) {
            int n  = 2 * ph + u;
            int bb = n * NB + b;
            const float4* __restrict__ metaB = g_meta + (size_t)bb * CELLS;
            const float*  __restrict__ pl    = (const float*)planes4[u];

#pragma unroll
            for (int j = 0; j < 8; j++) {
                int cell = t + 512 * j;
                float4 mt = metaB[cell];
                int p  = __float_as_int(mt.x);
                int y0 = p >> 16;
                int x0 = (p << 16) >> 16;
                float wv0 = mt.y, wv1 = mt.z, ax = mt.w;

                // Gather 4x4 patch with zero-outside semantics
                float v[4][4];
#pragma unroll
                for (int r = 0; r < 4; r++) {
                    int y = y0 - 1 + r;
                    bool ry = ((unsigned)y < (unsigned)SRC_HW);
                    int yb = (min(max(y, 0), SRC_HW - 1)) << 6;
#pragma unroll
                    for (int q = 0; q < 4; q++) {
                        int x = x0 - 1 + q;
                        bool rx = ((unsigned)x < (unsigned)SRC_HW);
                        float val = pl[yb + min(max(x, 0), SRC_HW - 1)];
                        v[r][q] = (ry && rx) ? val : 0.0f;
                    }
                }

                // Separable bilinear: horizontal lerps then vertical, mask folded in
                float h[4][3];
#pragma unroll
                for (int r = 0; r < 4; r++)
#pragma unroll
                    for (int q = 0; q < 3; q++)
                        h[r][q] = fmaf(ax, v[r][q + 1] - v[r][q], v[r][q]);

#pragma unroll
                for (int i = 0; i < 3; i++)
#pragma unroll
                    for (int q = 0; q < 3; q++) {
                        float a = acc[j][i * 3 + q];
                        a = fmaf(wv0, h[i][q], a);
                        a = fmaf(wv1, h[i + 1][q], a);
                        acc[j][i * 3 + q] = a;
                    }
            }
        }
        __syncthreads();
    }

    // Write 8 cells x 3x3 outputs
    float* ob = out + ((size_t)(b * CH + c)) * (HO * HO);
#pragma unroll
    for (int j = 0; j < 8; j++) {
        int cell = t + 512 * j;
        int cy = cell >> 6;
        int cx = cell & 63;
#pragma unroll
        for (int i = 0; i < 3; i++) {
            float* row = ob + (size_t)(cy * 3 + i) * HO + cx * 3;
            row[0] = acc[j][i * 3 + 0];
            row[1] = acc[j][i * 3 + 1];
            row[2] = acc[j][i * 3 + 2];
        }
    }
}

extern "C" void kernel_launch(void* const* d_in, const int* in_sizes, int n_in,
                              void* d_out, int out_size) {
    const float* src   = (const float*)d_in[0];  // (16, 256, 64, 64)
    const float* flow  = (const float*)d_in[1];  // (16, 2, 64, 64)
    const float* masks = (const float*)d_in[2];  // (16, 1, 64, 64)
    float* out = (float*)d_out;                  // (4, 256, 192, 192)

    meta_kernel<<<(NBB * CELLS + 255) / 256, 256>>>(flow, masks);

    dim3 grid(CH, NB);
    extract_kernel<<<grid, 512>>>(src, out);
}

// round 4
// speedup vs baseline: 1.2246x; 1.2246x over previous
#include <cuda_runtime.h>

// Problem constants
#define SRC_HW   64
#define CELLS    4096        // 64*64 flow cells per batch-slice
#define CH       256
#define NB       4           // output batches
#define NN       4           // accumulated slices (num)
#define HO       192         // output H = W = 3*64
#define NBB      16          // NB*NN batch-slices
#define PW       72          // padded plane width/height (4 zero border each side)

// Precomputed per-(bb, cell) metadata:
//  .x = bitcast int: SMEM word offset of patch base in padded 72x72 plane
//       off = (clamp(y0-1,-4,64)+4)*72 + (clamp(x0-1,-4,64)+4)
//  .y = m * (1 - ay)
//  .z = m * ay
//  .w = ax
__device__ float4 g_meta[NBB * CELLS];   // 1 MB static scratch

__global__ void meta_kernel(const float* __restrict__ flow,
                            const float* __restrict__ masks) {
    int idx = blockIdx.x * blockDim.x + threadIdx.x;
    if (idx >= NBB * CELLS) return;
    int bb   = idx >> 12;
    int cell = idx & (CELLS - 1);
    int cy = cell >> 6;
    int cx = cell & 63;

    float fy = flow[((size_t)(bb * 2 + 0)) * CELLS + cell];
    float fx = flow[((size_t)(bb * 2 + 1)) * CELLS + cell];
    float m  = masks[(size_t)bb * CELLS + cell];

    float by = (float)cy + fy;
    float bx = (float)cx + fx;
    float y0f = floorf(by);
    float x0f = floorf(bx);
    float ay = by - y0f;
    float ax = bx - x0f;
    int y0 = (int)y0f;
    int x0 = (int)x0f;

    // Clamp patch base into the padded plane. Any row/col that falls in the
    // 4-wide zero border reads exact zeros, matching zero-outside bilinear.
    int yb = min(max(y0 - 1, -4), SRC_HW);
    int xb = min(max(x0 - 1, -4), SRC_HW);
    int off = (yb + 4) * PW + (xb + 4);

    g_meta[idx] = make_float4(__int_as_float(off), m * (1.0f - ay), m * ay, ax);
}

// One block per (channel, batch, cell-half). Padded source plane staged in
// SMEM; per-cell gather is 16 LDS with immediate offsets off a precomputed
// base — zero per-tap address ALU, no predication.
__global__ __launch_bounds__(256, 2)
void extract_kernel(const float* __restrict__ src, float* __restrict__ out) {
    const int c = blockIdx.x;   // 0..255
    const int b = blockIdx.y;   // 0..3
    const int z = blockIdx.z;   // 0..1  (cell half)
    const int t = threadIdx.x;  // 0..255

    __shared__ float plane[PW * PW];   // 20736 B, zero-padded borders

    // Zero the whole buffer once; interior is overwritten each plane,
    // borders stay zero.
    for (int i = t; i < PW * PW; i += 256) plane[i] = 0.0f;

    float acc[8][9];
#pragma unroll
    for (int j = 0; j < 8; j++)
#pragma unroll
        for (int q = 0; q < 9; q++) acc[j][q] = 0.0f;

    const int cell0 = z * 2048;

    for (int n = 0; n < NN; n++) {
        __syncthreads();   // previous compute (or zero-fill) done before overwrite
        const int bb = n * NB + b;

        // Cooperative load: 64x64 plane into padded interior, STS.128
        const float4* sp = (const float4*)(src + ((size_t)(bb * CH + c)) * CELLS);
#pragma unroll
        for (int k = 0; k < 4; k++) {
            int i    = t + 256 * k;    // float4 index 0..1023
            int row  = i >> 4;         // 16 float4 per source row
            int col4 = i & 15;
            float4 v = sp[i];
            *(float4*)&plane[(row + 4) * PW + 4 + col4 * 4] = v;
        }
        __syncthreads();

        const float4* __restrict__ metaB = g_meta + (size_t)bb * CELLS + cell0;

#pragma unroll
        for (int j = 0; j < 8; j++) {
            float4 mt = metaB[t + 256 * j];
            const float* __restrict__ p = plane + __float_as_int(mt.x);
            float wv0 = mt.y, wv1 = mt.z, ax = mt.w;

            // 4x4 patch: pure LDS with immediate offsets
            float v[4][4];
#pragma unroll
            for (int r = 0; r < 4; r++)
#pragma unroll
                for (int q = 0; q < 4; q++)
                    v[r][q] = p[r * PW + q];

            // Separable bilinear: horizontal lerps, then masked vertical FMAs
            float h[4][3];
#pragma unroll
            for (int r = 0; r < 4; r++)
#pragma unroll
                for (int q = 0; q < 3; q++)
                    h[r][q] = fmaf(ax, v[r][q + 1] - v[r][q], v[r][q]);

#pragma unroll
            for (int i = 0; i < 3; i++)
#pragma unroll
                for (int q = 0; q < 3; q++) {
                    float a = acc[j][i * 3 + q];
                    a = fmaf(wv0, h[i][q], a);
                    a = fmaf(wv1, h[i + 1][q], a);
                    acc[j][i * 3 + q] = a;
                }
        }
    }

    // Write 8 cells x 3x3 outputs (adjacent threads -> adjacent 3-float groups)
    float* ob = out + ((size_t)(b * CH + c)) * (HO * HO);
#pragma unroll
    for (int j = 0; j < 8; j++) {
        int cell = cell0 + t + 256 * j;
        int cy = cell >> 6;
        int cx = cell & 63;
#pragma unroll
        for (int i = 0; i < 3; i++) {
            float* row = ob + (size_t)(cy * 3 + i) * HO + cx * 3;
            row[0] = acc[j][i * 3 + 0];
            row[1] = acc[j][i * 3 + 1];
            row[2] = acc[j][i * 3 + 2];
        }
    }
}

extern "C" void kernel_launch(void* const* d_in, const int* in_sizes, int n_in,
                              void* d_out, int out_size) {
    const float* src   = (const float*)d_in[0];  // (16, 256, 64, 64)
    const float* flow  = (const float*)d_in[1];  // (16, 2, 64, 64)
    const float* masks = (const float*)d_in[2];  // (16, 1, 64, 64)
    float* out = (float*)d_out;                  // (4, 256, 192, 192)

    meta_kernel<<<(NBB * CELLS + 255) / 256, 256>>>(flow, masks);

    dim3 grid(CH, NB, 2);
    extract_kernel<<<grid, 256>>>(src, out);
}

// round 5
// speedup vs baseline: 1.3527x; 1.1046x over previous
#include <cuda_runtime.h>

// Problem constants
#define SRC_HW   64
#define CELLS    4096        // 64*64 flow cells per batch-slice
#define CH       256
#define NB       4           // output batches
#define NN       4           // accumulated slices (num)
#define HO       192         // output H = W = 3*64
#define NBB      16          // NB*NN batch-slices
#define PW       72          // padded plane width/height (4 zero border each side)

// Precomputed per-(bb, cell) metadata:
//  .x = bitcast int: SMEM word offset of patch base in padded 72x72 plane
//       off = (clamp(y0-1,-4,64)+4)*72 + (clamp(x0-1,-4,64)+4)
//  .y = m * (1 - ay)
//  .z = m * ay
//  .w = ax
__device__ float4 g_meta[NBB * CELLS];   // 1 MB static scratch

__global__ void meta_kernel(const float* __restrict__ flow,
                            const float* __restrict__ masks) {
    int idx = blockIdx.x * blockDim.x + threadIdx.x;
    if (idx >= NBB * CELLS) return;
    int bb   = idx >> 12;
    int cell = idx & (CELLS - 1);
    int cy = cell >> 6;
    int cx = cell & 63;

    float fy = flow[((size_t)(bb * 2 + 0)) * CELLS + cell];
    float fx = flow[((size_t)(bb * 2 + 1)) * CELLS + cell];
    float m  = masks[(size_t)bb * CELLS + cell];

    float by = (float)cy + fy;
    float bx = (float)cx + fx;
    float y0f = floorf(by);
    float x0f = floorf(bx);
    float ay = by - y0f;
    float ax = bx - x0f;
    int y0 = (int)y0f;
    int x0 = (int)x0f;

    // Clamp patch base into the padded plane. Any row/col that falls in the
    // 4-wide zero border reads exact zeros, matching zero-outside bilinear.
    int yb = min(max(y0 - 1, -4), SRC_HW);
    int xb = min(max(x0 - 1, -4), SRC_HW);
    int off = (yb + 4) * PW + (xb + 4);

    g_meta[idx] = make_float4(__int_as_float(off), m * (1.0f - ay), m * ay, ax);
}

// One block per (channel, batch, cell-quarter). Padded source plane staged in
// SMEM; per-cell gather is 16 LDS with immediate offsets off a precomputed
// base. 4 cells/thread keeps accumulators at 36 regs so 3 CTAs/SM fit.
__global__ __launch_bounds__(256, 3)
void extract_kernel(const float* __restrict__ src, float* __restrict__ out) {
    const int c = blockIdx.x;   // 0..255
    const int b = blockIdx.y;   // 0..3
    const int z = blockIdx.z;   // 0..3  (cell quarter)
    const int t = threadIdx.x;  // 0..255

    __shared__ float plane[PW * PW];   // 20736 B, zero-padded borders

    // Zero the whole buffer once; interior is overwritten each plane,
    // borders stay zero.
    for (int i = t; i < PW * PW; i += 256) plane[i] = 0.0f;

    float acc[4][9];
#pragma unroll
    for (int j = 0; j < 4; j++)
#pragma unroll
        for (int q = 0; q < 9; q++) acc[j][q] = 0.0f;

    const int cell0 = z * 1024;

    for (int n = 0; n < NN; n++) {
        __syncthreads();   // previous compute (or zero-fill) done before overwrite
        const int bb = n * NB + b;

        // Cooperative load: 64x64 plane into padded interior, STS.128
        const float4* sp = (const float4*)(src + ((size_t)(bb * CH + c)) * CELLS);
#pragma unroll
        for (int k = 0; k < 4; k++) {
            int i    = t + 256 * k;    // float4 index 0..1023
            int row  = i >> 4;         // 16 float4 per source row
            int col4 = i & 15;
            float4 v = sp[i];
            *(float4*)&plane[(row + 4) * PW + 4 + col4 * 4] = v;
        }
        __syncthreads();

        const float4* __restrict__ metaB = g_meta + (size_t)bb * CELLS + cell0;

#pragma unroll
        for (int j = 0; j < 4; j++) {
            float4 mt = metaB[t + 256 * j];
            const float* __restrict__ p = plane + __float_as_int(mt.x);
            float wv0 = mt.y, wv1 = mt.z, ax = mt.w;

            // 4x4 patch: pure LDS with immediate offsets
            float v[4][4];
#pragma unroll
            for (int r = 0; r < 4; r++)
#pragma unroll
                for (int q = 0; q < 4; q++)
                    v[r][q] = p[r * PW + q];

            // Separable bilinear: horizontal lerps, then masked vertical FMAs
            float h[4][3];
#pragma unroll
            for (int r = 0; r < 4; r++)
#pragma unroll
                for (int q = 0; q < 3; q++)
                    h[r][q] = fmaf(ax, v[r][q + 1] - v[r][q], v[r][q]);

#pragma unroll
            for (int i = 0; i < 3; i++)
#pragma unroll
                for (int q = 0; q < 3; q++) {
                    float a = acc[j][i * 3 + q];
                    a = fmaf(wv0, h[i][q], a);
                    a = fmaf(wv1, h[i + 1][q], a);
                    acc[j][i * 3 + q] = a;
                }
        }
    }

    // Write 4 cells x 3x3 outputs (adjacent threads -> adjacent 3-float groups)
    float* ob = out + ((size_t)(b * CH + c)) * (HO * HO);
#pragma unroll
    for (int j = 0; j < 4; j++) {
        int cell = cell0 + t + 256 * j;
        int cy = cell >> 6;
        int cx = cell & 63;
#pragma unroll
        for (int i = 0; i < 3; i++) {
            float* row = ob + (size_t)(cy * 3 + i) * HO + cx * 3;
            row[0] = acc[j][i * 3 + 0];
            row[1] = acc[j][i * 3 + 1];
            row[2] = acc[j][i * 3 + 2];
        }
    }
}

extern "C" void kernel_launch(void* const* d_in, const int* in_sizes, int n_in,
                              void* d_out, int out_size) {
    const float* src   = (const float*)d_in[0];  // (16, 256, 64, 64)
    const float* flow  = (const float*)d_in[1];  // (16, 2, 64, 64)
    const float* masks = (const float*)d_in[2];  // (16, 1, 64, 64)
    float* out = (float*)d_out;                  // (4, 256, 192, 192)

    meta_kernel<<<(NBB * CELLS + 255) / 256, 256>>>(flow, masks);

    dim3 grid(CH, NB, 4);
    extract_kernel<<<grid, 256>>>(src, out);
}